// round 15
// baseline (speedup 1.0000x reference)
#include <cuda_runtime.h>
#include <cuda_fp16.h>
#include <cstdint>

#define HID   1024
#define TS1   1001            // TYPE_SIZE + 1 embedding rows
#define MPAD  1024
#define BATCH 32
#define SEQ   512
#define NTOK  (BATCH * SEQ)
#define NG    5               // used gates: gi, gz, go, gib, gd
#define NP    (NG * HID)      // 5120
#define WROW  2048            // W_rec row stride (2H)
#define KK    1024            // K (single-pass fp16)

#define NBLK    296           // one full resident wave at 2 CTAs/SM (148 SMs)
#define NGEMMB  148           // gemm-role blocks; rest are token-role
#define NTILE   256           // 16 bm-tiles x 16 bh-tiles
#define MAXPEND 128

// ---------------- device-global scratch (no allocs allowed) ----------------
__device__ __half g_A[MPAD * KK];            // 2 MB
__device__ __half g_B[NP * KK];              // 10 MB  slab g: 0=gi,1=gz,2=go,3=gib,4=gd
__device__ float g_table[TS1 * 4 * HID];     // 16.4 MB {c, c_bar, sig(go), sp(gd)}
__device__ int   g_tileTicket;               // gemm tile work-steal counter
__device__ int   g_tileCnt[16];              // per-e-tile completed bh-tile count (goal 16)

__constant__ int c_chunk[NG] = {0, 2, 3, 4, 6};   // gi, gz, go, gib, gd

// ---------------- base-target PTX helpers ----------------
__device__ __forceinline__ uint32_t smem_u32(const void* p) {
    uint32_t a;
    asm("{ .reg .u64 t; cvta.to.shared.u64 t, %1; cvt.u32.u64 %0, t; }"
        : "=r"(a) : "l"(p));
    return a;
}
#define CP_ASYNC16(dst, src) \
    asm volatile("cp.async.cg.shared.global [%0], [%1], 16;" \
                 :: "r"(dst), "l"(src))
#define CP_COMMIT() asm volatile("cp.async.commit_group;" ::: "memory")
#define CP_WAIT0()  asm volatile("cp.async.wait_group 0;" ::: "memory")
#define CP_WAIT1()  asm volatile("cp.async.wait_group 1;" ::: "memory")

__device__ __forceinline__ void ldsm_x4(uint32_t* r, uint32_t addr) {
    asm volatile("ldmatrix.sync.aligned.m8n8.x4.shared.b16 {%0,%1,%2,%3}, [%4];"
        : "=r"(r[0]), "=r"(r[1]), "=r"(r[2]), "=r"(r[3]) : "r"(addr));
}
__device__ __forceinline__ void mma_f16(float* c, const uint32_t* a,
                                        uint32_t b0, uint32_t b1) {
    asm volatile(
        "mma.sync.aligned.m16n8k16.row.col.f32.f16.f16.f32 "
        "{%0,%1,%2,%3}, {%4,%5,%6,%7}, {%8,%9}, {%0,%1,%2,%3};"
        : "+f"(c[0]), "+f"(c[1]), "+f"(c[2]), "+f"(c[3])
        : "r"(a[0]), "r"(a[1]), "r"(a[2]), "r"(a[3]), "r"(b0), "r"(b1));
}

// ---- fast transcendentals (MUFU) ----
#define LOG2E 1.4426950408889634f
#define LN2   0.6931471805599453f
__device__ __forceinline__ float ex2f(float x) {
    float y; asm("ex2.approx.f32 %0, %1;" : "=f"(y) : "f"(x)); return y;
}
__device__ __forceinline__ float lg2f(float x) {
    float y; asm("lg2.approx.f32 %0, %1;" : "=f"(y) : "f"(x)); return y;
}
__device__ __forceinline__ float rcpf(float x) {
    float y; asm("rcp.approx.f32 %0, %1;" : "=f"(y) : "f"(x)); return y;
}
__device__ __forceinline__ float fsigmoid(float x){ return rcpf(1.f + ex2f(-x * LOG2E)); }
__device__ __forceinline__ float fsoftplus(float x) {
    float e = ex2f(-fabsf(x) * LOG2E);
    return fmaxf(x, 0.f) + LN2 * lg2f(1.f + e);
}

// ---------------------------------------------------------------------------
// Conversion kernel (also zero-inits the work-steal / readiness state)
// ---------------------------------------------------------------------------
#define CONV_TOT (MPAD * HID + NP * HID)

__global__ __launch_bounds__(256)
void conv_AB(const float* __restrict__ emb, const float* __restrict__ W) {
    if (blockIdx.x == 0 && threadIdx.x < 17) {
        if (threadIdx.x == 16) g_tileTicket = 0;
        else                   g_tileCnt[threadIdx.x] = 0;
    }
    int idx = blockIdx.x * 256 + threadIdx.x;
    if (idx < MPAD * HID) {
        int e = idx >> 10;
        float a = (e < TS1) ? emb[idx] : 0.f;
        g_A[idx] = __float2half_rn(a);
    } else {
        int j = idx - MPAD * HID;
        if (j < NP * HID) {
            int n = j >> 10, k = j & 1023;
            int c = n >> 10, h = n & 1023;
            float a = W[(size_t)(c_chunk[c] * HID + h) * WROW + k];
            g_B[j] = __float2half_rn(a);
        }
    }
}

// ---------------------------------------------------------------------------
// FUSED persistent kernel: 148 gemm-role blocks (work-steal tiles, publish
// readiness) + 148 token-role blocks (process tokens as tiles become ready).
// ---------------------------------------------------------------------------
#define BK      32
#define KT      (KK / BK)                 // 32
#define TILE_B  (64 * 80)                 // 5120 B per 64-row tile per stage
#define STG_B   (6 * TILE_B)              // 30720 B per stage
#define SMEM_SZ (3 * STG_B)               // 92160 B dynamic

__global__ __launch_bounds__(256, 2)
void fused(const float* __restrict__ brec, const int* __restrict__ ev,
           const float* __restrict__ dur, float* __restrict__ out) {
    extern __shared__ __align__(16) char smem[];
    const uint32_t sbase = smem_u32(smem);
    __shared__ int s_val;
    __shared__ int s_pend[MAXPEND];

    const int blk = blockIdx.x;
    const int tid = threadIdx.x;
    const int wid = tid >> 5, lane = tid & 31;

    if (blk < NGEMMB) {
        // ==================== GEMM role ====================
        const int lrow = tid >> 2, lch = tid & 3;
        const uint32_t lmoff = (lane & 15) * 80 + (lane >> 4) * 16;
        const int wm = (wid & 1) * 32;             // warp m offset: 0,32
        const int wn = (wid >> 1) * 16;            // warp n offset: 0..48
        const int cm = lane >> 2, cn = (lane & 3) * 2;

        while (true) {
            if (tid == 0) s_val = atomicAdd(&g_tileTicket, 1);
            __syncthreads();
            const int tile = s_val;
            __syncthreads();
            if (tile >= NTILE) break;
            // bm-major ticket order: e-tiles complete as early as possible
            const int bm = (tile >> 4) * 64;
            const int bh = (tile & 15) * 64;

            const __half* gA = g_A + (size_t)bm * KK;
            const __half* gB = g_B + (size_t)bh * KK;

            float acc[NG][4][4];
#pragma unroll
            for (int g = 0; g < NG; g++)
#pragma unroll
                for (int j = 0; j < 4; j++)
#pragma unroll
                    for (int v = 0; v < 4; v++) acc[g][j][v] = 0.f;

            auto issue = [&](int kt, int s) {
                const int k0 = kt * BK;
                const uint32_t st = sbase + s * STG_B;
                const uint32_t doff = lrow * 80 + lch * 16;
                const size_t   soff = (size_t)lrow * KK + k0 + lch * 8;
                CP_ASYNC16(st + doff, gA + soff);
#pragma unroll
                for (int g = 0; g < NG; g++)
                    CP_ASYNC16(st + (g + 1) * TILE_B + doff,
                               gB + (size_t)g * HID * KK + soff);
            };

            issue(0, 0); CP_COMMIT();
            issue(1, 1); CP_COMMIT();

            int s = 0;
            for (int kt = 0; kt < KT; kt++) {
                if (kt < KT - 1) CP_WAIT1(); else CP_WAIT0();
                __syncthreads();

                const uint32_t aBase = sbase + s * STG_B;
#pragma unroll
                for (int ks = 0; ks < 2; ks++) {
                    uint32_t af[2][4];
                    ldsm_x4(af[0], aBase + (wm +  0) * 80 + ks * 32 + lmoff);
                    ldsm_x4(af[1], aBase + (wm + 16) * 80 + ks * 32 + lmoff);
                    if (ks == 0 && kt + 2 < KT) {
                        int s2 = s + 2; if (s2 >= 3) s2 -= 3;
                        issue(kt + 2, s2);
                        CP_COMMIT();
                    }
#pragma unroll
                    for (int g = 0; g < NG; g++) {
                        uint32_t bf[4];
                        ldsm_x4(bf, aBase + (g + 1) * TILE_B + wn * 80 + ks * 32 + lmoff);
                        mma_f16(acc[g][0], af[0], bf[0], bf[2]);
                        mma_f16(acc[g][1], af[0], bf[1], bf[3]);
                        mma_f16(acc[g][2], af[1], bf[0], bf[2]);
                        mma_f16(acc[g][3], af[1], bf[1], bf[3]);
                    }
                }
                if (++s == 3) s = 0;
            }

            // ---- activation epilogue -> g_table ----
#pragma unroll
            for (int mf = 0; mf < 2; mf++) {
#pragma unroll
                for (int nf = 0; nf < 2; nf++) {
                    const int j = mf * 2 + nf;
                    const int col = bh + wn + nf * 8 + cn;
                    const float2 bgi = *reinterpret_cast<const float2*>(brec + 0 * HID + col);
                    const float2 bgz = *reinterpret_cast<const float2*>(brec + 2 * HID + col);
                    const float2 bgo = *reinterpret_cast<const float2*>(brec + 3 * HID + col);
                    const float2 bgb = *reinterpret_cast<const float2*>(brec + 4 * HID + col);
                    const float2 bgd = *reinterpret_cast<const float2*>(brec + 6 * HID + col);
#pragma unroll
                    for (int half = 0; half < 2; half++) {
                        const int e = bm + wm + mf * 16 + cm + half * 8;
                        if (e >= TS1) continue;
                        const int v = half * 2;
                        float gi0 = acc[0][j][v] + bgi.x, gi1 = acc[0][j][v + 1] + bgi.y;
                        float gz0 = acc[1][j][v] + bgz.x, gz1 = acc[1][j][v + 1] + bgz.y;
                        float go0 = acc[2][j][v] + bgo.x, go1 = acc[2][j][v + 1] + bgo.y;
                        float gb0 = acc[3][j][v] + bgb.x, gb1 = acc[3][j][v + 1] + bgb.y;
                        float gd0 = acc[4][j][v] + bgd.x, gd1 = acc[4][j][v + 1] + bgd.y;

                        float tz0 = tanhf(gz0), tz1 = tanhf(gz1);
                        float* T = g_table + (size_t)e * (4 * HID) + col;
                        *reinterpret_cast<float2*>(T + 0 * HID) =
                            make_float2(fsigmoid(gi0) * tz0, fsigmoid(gi1) * tz1);
                        *reinterpret_cast<float2*>(T + 1 * HID) =
                            make_float2(fsigmoid(gb0) * tz0, fsigmoid(gb1) * tz1);
                        *reinterpret_cast<float2*>(T + 2 * HID) =
                            make_float2(fsigmoid(go0), fsigmoid(go1));
                        *reinterpret_cast<float2*>(T + 3 * HID) =
                            make_float2(fsoftplus(gd0), fsoftplus(gd1));
                    }
                }
            }

            // publish: all stores visible, then bump e-tile counter
            __threadfence();
            __syncthreads();
            if (tid == 0) atomicAdd(&g_tileCnt[tile >> 4], 1);
        }
        return;
    }

    // ==================== TOKEN role ====================
    const int my0 = blk - NGEMMB;                  // 0..147
    unsigned doneMask = 0;
    int npend = 0;
    const size_t stride = (size_t)SEQ * BATCH * HID;
    const int h = tid * 4;

    // ready-check with per-block cache; uniform result via smem broadcast
    auto check_tile = [&](int tile) -> int {
        if ((doneMask >> tile) & 1) return 1;
        if (tid == 0) s_val = ((*(volatile int*)&g_tileCnt[tile]) >= 16) ? 1 : 0;
        __syncthreads();
        const int ok = s_val;
        __syncthreads();
        if (ok) { __threadfence(); doneMask |= (1u << tile); }
        return ok;
    };

    auto process = [&](int tok, int e, float d) {
        const float dl = -d * LOG2E;
        const float* T = g_table + (size_t)e * (4 * HID);
        float4 c  = *reinterpret_cast<const float4*>(T + 0 * HID + h);
        float4 cb = *reinterpret_cast<const float4*>(T + 1 * HID + h);
        float4 go = *reinterpret_cast<const float4*>(T + 2 * HID + h);
        float4 gd = *reinterpret_cast<const float4*>(T + 3 * HID + h);
        float4 hd;
        hd.x = go.x * tanhf(cb.x + (c.x - cb.x) * ex2f(gd.x * dl));
        hd.y = go.y * tanhf(cb.y + (c.y - cb.y) * ex2f(gd.y * dl));
        hd.z = go.z * tanhf(cb.z + (c.z - cb.z) * ex2f(gd.z * dl));
        hd.w = go.w * tanhf(cb.w + (c.w - cb.w) * ex2f(gd.w * dl));
        float* base = out + (size_t)tok * HID + h;
        __stcs(reinterpret_cast<float4*>(base + 0 * stride), hd);
        __stcs(reinterpret_cast<float4*>(base + 1 * stride), c);
        __stcs(reinterpret_cast<float4*>(base + 2 * stride), cb);
        __stcs(reinterpret_cast<float4*>(base + 3 * stride), go);
        __stcs(reinterpret_cast<float4*>(base + 4 * stride), gd);
    };

    // pass 0: sweep own tokens, process ready ones, pend the rest
    for (int tok = my0; tok < NTOK; tok += NGEMMB) {
        const int t = tok >> 5, b = tok & 31;
        const int e = ev[b * SEQ + t];
        if (check_tile(e >> 6)) {
            process(tok, e, dur[b * SEQ + t]);
        } else {
            if (tid == 0) s_pend[npend] = tok;
            npend++;                               // uniform across threads
        }
    }

    // retry passes over pending list (in-place compaction)
    while (npend > 0) {
        __syncthreads();                           // make s_pend writes visible
        int newn = 0;
        for (int i = 0; i < npend; i++) {
            const int tok = s_pend[i];
            const int t = tok >> 5, b = tok & 31;
            const int e = ev[b * SEQ + t];
            if (check_tile(e >> 6)) {
                process(tok, e, dur[b * SEQ + t]);
            } else {
                if (tid == 0) s_pend[newn] = tok;  // newn <= i: safe
                newn++;
            }
        }
        npend = newn;
        if (npend) __nanosleep(1000);
    }
}

// ---------------------------------------------------------------------------
extern "C" void kernel_launch(void* const* d_in, const int* in_sizes, int n_in,
                              void* d_out, int out_size) {
    const int*   ev  = (const int*)  d_in[0];   // event_seqs   [32, 512] int32
    const float* dur = (const float*)d_in[1];   // duration_seqs[32, 512]
    const float* emb = (const float*)d_in[2];   // emb_table [1001, 1024]
    const float* W   = (const float*)d_in[3];   // W_rec [7168, 2048]
    const float* br  = (const float*)d_in[4];   // b_rec [7168]
    float* out = (float*)d_out;                 // [5, 512, 32, 1024]

    static bool init_done = false;
    if (!init_done) {
        cudaFuncSetAttribute(fused, cudaFuncAttributeMaxDynamicSharedMemorySize,
                             SMEM_SZ);
        init_done = true;
    }

    conv_AB<<<(CONV_TOT + 255) / 256, 256>>>(emb, W);
    fused<<<NBLK, 256, SMEM_SZ>>>(br, ev, dur, out);
}

// round 17
// speedup vs baseline: 1.5309x; 1.5309x over previous
#include <cuda_runtime.h>
#include <cuda_fp16.h>
#include <cstdint>

#define HID   1024
#define TS1   1001            // TYPE_SIZE + 1 embedding rows
#define MPAD  1024            // padded M (16 tiles of 64)
#define BATCH 32
#define SEQ   512
#define NTOK  (BATCH * SEQ)
#define NG    5               // used gates: gi, gz, go, gib, gd
#define NP    (NG * HID)      // 5120
#define WROW  2048            // W_rec row stride (2H)
#define KK    1024            // K (single-pass fp16)

// ---------------- device-global scratch (no allocs allowed) ----------------
__device__ __half g_A[MPAD * KK];            // 2 MB
__device__ __half g_B[NP * KK];              // 10 MB  slab g: 0=gi,1=gz,2=go,3=gib,4=gd
// fp16 gate-interleaved table: [e][h][4] = {c, c_bar, sig(go), sp(gd)}
__device__ __half g_tableH[TS1 * HID * 4];   // 8.2 MB

__constant__ int c_chunk[NG] = {0, 2, 3, 4, 6};   // gi, gz, go, gib, gd

// ---------------- base-target PTX helpers ----------------
__device__ __forceinline__ uint32_t smem_u32(const void* p) {
    uint32_t a;
    asm("{ .reg .u64 t; cvta.to.shared.u64 t, %1; cvt.u32.u64 %0, t; }"
        : "=r"(a) : "l"(p));
    return a;
}
#define CP_ASYNC16(dst, src) \
    asm volatile("cp.async.cg.shared.global [%0], [%1], 16;" \
                 :: "r"(dst), "l"(src))
#define CP_COMMIT() asm volatile("cp.async.commit_group;" ::: "memory")
#define CP_WAIT0()  asm volatile("cp.async.wait_group 0;" ::: "memory")
#define CP_WAIT1()  asm volatile("cp.async.wait_group 1;" ::: "memory")

__device__ __forceinline__ void ldsm_x4(uint32_t* r, uint32_t addr) {
    asm volatile("ldmatrix.sync.aligned.m8n8.x4.shared.b16 {%0,%1,%2,%3}, [%4];"
        : "=r"(r[0]), "=r"(r[1]), "=r"(r[2]), "=r"(r[3]) : "r"(addr));
}
__device__ __forceinline__ void mma_f16(float* c, const uint32_t* a,
                                        uint32_t b0, uint32_t b1) {
    asm volatile(
        "mma.sync.aligned.m16n8k16.row.col.f32.f16.f16.f32 "
        "{%0,%1,%2,%3}, {%4,%5,%6,%7}, {%8,%9}, {%0,%1,%2,%3};"
        : "+f"(c[0]), "+f"(c[1]), "+f"(c[2]), "+f"(c[3])
        : "r"(a[0]), "r"(a[1]), "r"(a[2]), "r"(a[3]), "r"(b0), "r"(b1));
}

// ---- fast transcendentals (MUFU) ----
#define LOG2E 1.4426950408889634f
#define LN2   0.6931471805599453f
__device__ __forceinline__ float ex2f(float x) {
    float y; asm("ex2.approx.f32 %0, %1;" : "=f"(y) : "f"(x)); return y;
}
__device__ __forceinline__ float lg2f(float x) {
    float y; asm("lg2.approx.f32 %0, %1;" : "=f"(y) : "f"(x)); return y;
}
__device__ __forceinline__ float rcpf(float x) {
    float y; asm("rcp.approx.f32 %0, %1;" : "=f"(y) : "f"(x)); return y;
}
__device__ __forceinline__ float fsigmoid(float x){ return rcpf(1.f + ex2f(-x * LOG2E)); }
__device__ __forceinline__ float fsoftplus(float x) {
    float e = ex2f(-fabsf(x) * LOG2E);
    return fmaxf(x, 0.f) + LN2 * lg2f(1.f + e);
}

// ---------------------------------------------------------------------------
// Merged conversion kernel: A then B region in one launch
// ---------------------------------------------------------------------------
#define CONV_TOT (MPAD * HID + NP * HID)

__global__ __launch_bounds__(256)
void conv_AB(const float* __restrict__ emb, const float* __restrict__ W) {
    int idx = blockIdx.x * 256 + threadIdx.x;
    if (idx < MPAD * HID) {
        int e = idx >> 10;
        float a = (e < TS1) ? emb[idx] : 0.f;
        g_A[idx] = __float2half_rn(a);
    } else {
        int j = idx - MPAD * HID;
        if (j < NP * HID) {
            int n = j >> 10, k = j & 1023;
            int c = n >> 10, h = n & 1023;
            float a = W[(size_t)(c_chunk[c] * HID + h) * WROW + k];
            g_B[j] = __float2half_rn(a);
        }
    }
}

// ---------------------------------------------------------------------------
// GEMM (full): 5-gate fp16 GEMM + activation epilogue -> g_tableH.
// Grid (16,16) = 256 blocks -> 2 CTAs/SM. Warps 2(m) x 4(n).
// Epilogue: one 16B interleaved fp16 store per (e, h-pair) per fragment.
// ---------------------------------------------------------------------------
#define BK      32
#define KT      (KK / BK)                 // 32
#define TILE_B  (64 * 80)                 // 5120 B per 64-row tile per stage
#define STG_B   (6 * TILE_B)              // 30720 B per stage
#define SMEM_SZ (3 * STG_B)               // 92160 B  (x2 CTAs <= 228KB)

__global__ __launch_bounds__(256, 2)
void gemm_full(const float* __restrict__ brec) {
    extern __shared__ __align__(16) char smem[];
    const uint32_t sbase = smem_u32(smem);

    const int tid = threadIdx.x;
    const int wid = tid >> 5, lane = tid & 31;
    const int bh = blockIdx.x * 64;            // h-tile (within HID)
    const int bm = blockIdx.y * 64;            // e-tile
    const int wm = (wid & 1) * 32;             // warp m offset: 0,32
    const int wn = (wid >> 1) * 16;            // warp n offset: 0,16,32,48

    const __half* gA = g_A + (size_t)bm * KK;
    const __half* gB = g_B + (size_t)bh * KK;

    const int lrow = tid >> 2, lch = tid & 3;

    auto issue = [&](int kt, int s) {
        const int k0 = kt * BK;
        const uint32_t st = sbase + s * STG_B;
        const uint32_t doff = lrow * 80 + lch * 16;
        const size_t   soff = (size_t)lrow * KK + k0 + lch * 8;
        CP_ASYNC16(st + doff, gA + soff);
#pragma unroll
        for (int g = 0; g < NG; g++)
            CP_ASYNC16(st + (g + 1) * TILE_B + doff,
                       gB + (size_t)g * HID * KK + soff);
    };

    float acc[NG][4][4];
#pragma unroll
    for (int g = 0; g < NG; g++)
#pragma unroll
        for (int j = 0; j < 4; j++)
#pragma unroll
            for (int v = 0; v < 4; v++) acc[g][j][v] = 0.f;

    issue(0, 0); CP_COMMIT();
    issue(1, 1); CP_COMMIT();

    const uint32_t lmoff = (lane & 15) * 80 + (lane >> 4) * 16;

    int s = 0;
    for (int kt = 0; kt < KT; kt++) {
        if (kt < KT - 1) CP_WAIT1(); else CP_WAIT0();
        __syncthreads();

        const uint32_t aBase = sbase + s * STG_B;

#pragma unroll
        for (int ks = 0; ks < 2; ks++) {
            uint32_t af[2][4];
            ldsm_x4(af[0], aBase + (wm +  0) * 80 + ks * 32 + lmoff);
            ldsm_x4(af[1], aBase + (wm + 16) * 80 + ks * 32 + lmoff);
            if (ks == 0 && kt + 2 < KT) {
                int s2 = s + 2; if (s2 >= 3) s2 -= 3;
                issue(kt + 2, s2);
                CP_COMMIT();
            }
#pragma unroll
            for (int g = 0; g < NG; g++) {
                uint32_t bf[4];
                ldsm_x4(bf, aBase + (g + 1) * TILE_B + wn * 80 + ks * 32 + lmoff);
                mma_f16(acc[g][0], af[0], bf[0], bf[2]);   // mf0 nf0
                mma_f16(acc[g][1], af[0], bf[1], bf[3]);   // mf0 nf1
                mma_f16(acc[g][2], af[1], bf[0], bf[2]);   // mf1 nf0
                mma_f16(acc[g][3], af[1], bf[1], bf[3]);   // mf1 nf1
            }
        }
        if (++s == 3) s = 0;
    }

    // ---- fused activation epilogue -> fp16 interleaved table ----
    // Thread covers cols (col, col+1) for rows e, e+8 per (mf, nf) fragment.
    const int cm = lane >> 2, cn = (lane & 3) * 2;

#pragma unroll
    for (int mf = 0; mf < 2; mf++) {
#pragma unroll
        for (int nf = 0; nf < 2; nf++) {
            const int j = mf * 2 + nf;
            const int col = bh + wn + nf * 8 + cn;
            const float2 bgi = *reinterpret_cast<const float2*>(brec + 0 * HID + col);
            const float2 bgz = *reinterpret_cast<const float2*>(brec + 2 * HID + col);
            const float2 bgo = *reinterpret_cast<const float2*>(brec + 3 * HID + col);
            const float2 bgb = *reinterpret_cast<const float2*>(brec + 4 * HID + col);
            const float2 bgd = *reinterpret_cast<const float2*>(brec + 6 * HID + col);
#pragma unroll
            for (int half = 0; half < 2; half++) {
                const int e = bm + wm + mf * 16 + cm + half * 8;
                if (e >= TS1) continue;
                const int v = half * 2;
                float gi0 = acc[0][j][v] + bgi.x, gi1 = acc[0][j][v + 1] + bgi.y;
                float gz0 = acc[1][j][v] + bgz.x, gz1 = acc[1][j][v + 1] + bgz.y;
                float go0 = acc[2][j][v] + bgo.x, go1 = acc[2][j][v + 1] + bgo.y;
                float gb0 = acc[3][j][v] + bgb.x, gb1 = acc[3][j][v + 1] + bgb.y;
                float gd0 = acc[4][j][v] + bgd.x, gd1 = acc[4][j][v + 1] + bgd.y;

                float tz0 = tanhf(gz0), tz1 = tanhf(gz1);
                // interleaved: {c, cb, go, gd} per h; two h per store = 16 B
                __half2 p0 = __floats2half2_rn(fsigmoid(gi0) * tz0,
                                               fsigmoid(gb0) * tz0);
                __half2 p1 = __floats2half2_rn(fsigmoid(go0), fsoftplus(gd0));
                __half2 p2 = __floats2half2_rn(fsigmoid(gi1) * tz1,
                                               fsigmoid(gb1) * tz1);
                __half2 p3 = __floats2half2_rn(fsigmoid(go1), fsoftplus(gd1));

                uint4 val = make_uint4(*(uint32_t*)&p0, *(uint32_t*)&p1,
                                       *(uint32_t*)&p2, *(uint32_t*)&p3);
                *reinterpret_cast<uint4*>(
                    g_tableH + (size_t)e * (HID * 4) + col * 4) = val;
            }
        }
    }
}

// ---------------------------------------------------------------------------
// Token kernel: per-token gather (2x16B contiguous loads) + decay + 5 outputs
// ---------------------------------------------------------------------------
__global__ __launch_bounds__(256)
void token_kernel(const int* __restrict__ ev, const float* __restrict__ dur,
                  float* __restrict__ out) {
    const int tok = blockIdx.x;        // = t*BATCH + b (matches output layout)
    const int t = tok >> 5;
    const int b = tok & 31;

    const int   e = ev[b * SEQ + t];   // inputs are [B, T]
    const float d = dur[b * SEQ + t];
    const float dl = -d * LOG2E;       // exp(-gd*d) = ex2(gd * dl)

    const int h = threadIdx.x * 4;
    const uint4* Tp = reinterpret_cast<const uint4*>(
        g_tableH + (size_t)e * (HID * 4) + h * 4);
    uint4 r0 = Tp[0];                  // h, h+1
    uint4 r1 = Tp[1];                  // h+2, h+3

    float2 ccb0 = __half22float2(*reinterpret_cast<__half2*>(&r0.x));
    float2 ogd0 = __half22float2(*reinterpret_cast<__half2*>(&r0.y));
    float2 ccb1 = __half22float2(*reinterpret_cast<__half2*>(&r0.z));
    float2 ogd1 = __half22float2(*reinterpret_cast<__half2*>(&r0.w));
    float2 ccb2 = __half22float2(*reinterpret_cast<__half2*>(&r1.x));
    float2 ogd2 = __half22float2(*reinterpret_cast<__half2*>(&r1.y));
    float2 ccb3 = __half22float2(*reinterpret_cast<__half2*>(&r1.z));
    float2 ogd3 = __half22float2(*reinterpret_cast<__half2*>(&r1.w));

    float4 c  = make_float4(ccb0.x, ccb1.x, ccb2.x, ccb3.x);
    float4 cb = make_float4(ccb0.y, ccb1.y, ccb2.y, ccb3.y);
    float4 go = make_float4(ogd0.x, ogd1.x, ogd2.x, ogd3.x);
    float4 gd = make_float4(ogd0.y, ogd1.y, ogd2.y, ogd3.y);

    float4 hd;
    hd.x = go.x * tanhf(cb.x + (c.x - cb.x) * ex2f(gd.x * dl));
    hd.y = go.y * tanhf(cb.y + (c.y - cb.y) * ex2f(gd.y * dl));
    hd.z = go.z * tanhf(cb.z + (c.z - cb.z) * ex2f(gd.z * dl));
    hd.w = go.w * tanhf(cb.w + (c.w - cb.w) * ex2f(gd.w * dl));

    const size_t stride = (size_t)SEQ * BATCH * HID;
    float* base = out + (size_t)tok * HID + h;

    __stcs(reinterpret_cast<float4*>(base + 0 * stride), hd);
    __stcs(reinterpret_cast<float4*>(base + 1 * stride), c);
    __stcs(reinterpret_cast<float4*>(base + 2 * stride), cb);
    __stcs(reinterpret_cast<float4*>(base + 3 * stride), go);
    __stcs(reinterpret_cast<float4*>(base + 4 * stride), gd);
}

// ---------------------------------------------------------------------------
extern "C" void kernel_launch(void* const* d_in, const int* in_sizes, int n_in,
                              void* d_out, int out_size) {
    const int*   ev  = (const int*)  d_in[0];   // event_seqs   [32, 512] int32
    const float* dur = (const float*)d_in[1];   // duration_seqs[32, 512]
    const float* emb = (const float*)d_in[2];   // emb_table [1001, 1024]
    const float* W   = (const float*)d_in[3];   // W_rec [7168, 2048]
    const float* br  = (const float*)d_in[4];   // b_rec [7168]
    float* out = (float*)d_out;                 // [5, 512, 32, 1024]

    static bool init_done = false;
    if (!init_done) {
        cudaFuncSetAttribute(gemm_full,
                             cudaFuncAttributeMaxDynamicSharedMemorySize,
                             SMEM_SZ);
        init_done = true;
    }

    conv_AB<<<(CONV_TOT + 255) / 256, 256>>>(emb, W);

    dim3 g1(HID / 64, MPAD / 64);               // (16, 16) = 256 blocks
    gemm_full<<<g1, 256, SMEM_SZ>>>(br);

    token_kernel<<<NTOK, 256>>>(ev, dur, out);
}